// round 12
// baseline (speedup 1.0000x reference)
#include <cuda_runtime.h>
#include <cstdint>

#define S_  1024
#define B_  64
#define I_  256
#define H_  512
#define NC  128      // persistent CTAs (16 h-groups x 8 b-groups)
#define NHG 16

// ---------------- scratch (static __device__ — no allocation) ----------------
__device__ float  g_f[2][B_][H_];                 // tanh(u) exchange, double-buffered
__device__ float4 g_part4[2][B_][NHG][2];         // 6 partial sums per (b, hgroup)
__device__ unsigned long long g_tickets;          // barrier arrivals (monotonic u64)

// ---- packed fp32x2 helpers (Blackwell dual-issue fp32) ----
#define FMA2(d, a, b) \
    asm("fma.rn.f32x2 %0, %1, %2, %0;" : "+l"(d) : "l"(a), "l"(b))

__device__ __forceinline__ unsigned long long pk2(float a, float b) {
    return (unsigned long long)__float_as_uint(a) |
           ((unsigned long long)__float_as_uint(b) << 32);
}
__device__ __forceinline__ float fold2(unsigned long long v) {
    return __uint_as_float((unsigned)v) + __uint_as_float((unsigned)(v >> 32));
}
// XOR swizzle on a 512-float h row (16B granularity) -> conflict-free LDS.128
__device__ __forceinline__ int hswz(int f) {
    int u = f >> 2;
    u ^= (u >> 3) & 7;
    return (u << 2) | (f & 3);
}
// XOR swizzle on 64 float4-slots of a 256-float row (involution)
__device__ __forceinline__ int sw64(int s) { return s ^ ((s >> 3) & 7); }

// fast tanh: (1 - e^{-2|x|}) / (1 + e^{-2|x|}), sign-restored (~1e-6 abs err)
__device__ __forceinline__ float tanh_f(float x) {
    float e = __expf(-2.f * fabsf(x));
    float t = __fdividef(1.f - e, 1.f + e);
    return copysignf(t, x);
}

// 16-value butterfly reduce over 32 lanes; result valid on even lanes,
// value index = (lane>>1)&15 (idx = op*4 + b4).
__device__ __forceinline__ float butterfly16(float r[16], int lane) {
    int up = lane & 16;
    #pragma unroll
    for (int i = 0; i < 8; i++) {
        float snd = up ? r[i] : r[i + 8];
        float kp  = up ? r[i + 8] : r[i];
        r[i] = kp + __shfl_xor_sync(0xffffffffu, snd, 16);
    }
    up = lane & 8;
    #pragma unroll
    for (int i = 0; i < 4; i++) {
        float snd = up ? r[i] : r[i + 4];
        float kp  = up ? r[i + 4] : r[i];
        r[i] = kp + __shfl_xor_sync(0xffffffffu, snd, 8);
    }
    up = lane & 4;
    #pragma unroll
    for (int i = 0; i < 2; i++) {
        float snd = up ? r[i] : r[i + 2];
        float kp  = up ? r[i + 2] : r[i];
        r[i] = kp + __shfl_xor_sync(0xffffffffu, snd, 4);
    }
    {
        int u2 = lane & 2;
        float snd = u2 ? r[0] : r[1];
        float kp  = u2 ? r[1] : r[0];
        r[0] = kp + __shfl_xor_sync(0xffffffffu, snd, 2);
    }
    r[0] += __shfl_xor_sync(0xffffffffu, r[0], 1);
    return r[0];
}

// ---------------- dynamic SMEM layout (bytes) ----------------
#define OFF_H     0          // h_s      : 8 x 512 f                (16384)
#define OFF_X     16384      // x_s      : 2 x 8 x 256 f            (16384)
#define OFF_W     32768      // w_s      : 64 x 256 f               (65536)
#define OFF_PA    98304      // pa_s     : 2 x 8 x 32 f             (2048)
#define OFF_PC    100352     // pc_s     : 2 x 8 x 32 f             (2048)
#define OFF_VAL   102400     // val_s    : 8 x 64 f                 (2048)
#define OFF_GAM   104448     // gam_s    : 512 f                    (2048)
#define OFF_BET   106496     // bet_s    : 512 f                    (2048)
#define OFF_ST    108544     // stats_s  : 8 float4                 (128)
#define OFF_W2    108672     // w2_s     : 32 f                     (128)
#define OFF_BIAS  108800     // bias_s   : 64 f                     (256)
#define SMEM_TOT  109056

// =============================================================================
// Single persistent kernel: recurrent scan with the input-GEMM (A/C tiles)
// fused into the inter-CTA barrier window.
// =============================================================================
__global__ __launch_bounds__(512, 1) void liquid_recurrent(
    const float* __restrict__ x,      const float* __restrict__ h0,
    const float* __restrict__ W_in,   const float* __restrict__ b_in,
    const float* __restrict__ W_rec,  const float* __restrict__ tau_w1,
    const float* __restrict__ tau_b1, const float* __restrict__ tau_w2,
    const float* __restrict__ tau_b2, const float* __restrict__ gamma,
    const float* __restrict__ beta,
    float* __restrict__ out, float* __restrict__ hfin, float* __restrict__ tauh)
{
    extern __shared__ __align__(16) char smem[];
    float* h_s   = (float*)(smem + OFF_H);
    float* x_s   = (float*)(smem + OFF_X);
    float* w_s   = (float*)(smem + OFF_W);
    float (*pa_s)[8][32] = (float(*)[8][32])(smem + OFF_PA);
    float (*pc_s)[8][32] = (float(*)[8][32])(smem + OFF_PC);
    float (*val_s)[64]   = (float(*)[64])(smem + OFF_VAL);
    float* gam_s = (float*)(smem + OFF_GAM);
    float* bet_s = (float*)(smem + OFF_BET);
    float4* stats_s = (float4*)(smem + OFF_ST);
    float* w2_s  = (float*)(smem + OFF_W2);
    float* bias_s = (float*)(smem + OFF_BIAS);

    const int tid  = threadIdx.x;
    const int hg   = blockIdx.x & 15;
    const int bg   = blockIdx.x >> 4;
    const int warp = tid >> 5, lane = tid & 31;
    const bool is_rec = (warp < 8);
    const int jlb  = (warp & 7) * 4;                // jl base for this warp

    // ---- recurrent weights -> registers as f32x2 k-pairs (64 regs) ----
    unsigned long long w2r[32];
    {
        #pragma unroll
        for (int op = 0; op < 4; op++) {
            int j = hg * 32 + jlb + op;
            const float* wr = is_rec ? (W_rec + (size_t)j * H_)
                                     : (tau_w1 + (size_t)j * (I_ + H_) + I_);
            #pragma unroll
            for (int p4 = 0; p4 < 4; p4++) {
                float4 v = *(const float4*)(wr + lane * 16 + p4 * 4);
                w2r[op * 8 + p4 * 2]     = pk2(v.x, v.y);
                w2r[op * 8 + p4 * 2 + 1] = pk2(v.z, v.w);
            }
        }
    }
    const int s3 = (lane >> 1) & 7;
    int hoff[4];
    #pragma unroll
    for (int p4 = 0; p4 < 4; p4++) hoff[p4] = ((lane * 4 + p4) ^ s3) << 2;
    const int sw_tid = hswz(tid);
    const int sw_j   = hswz(hg * 32 + lane);
    const int xs0 = sw64(lane * 2);                 // physical slot of logical 2*lane
    const int xs1 = xs0 ^ 1;                        // physical slot of logical 2*lane+1

    gam_s[tid] = gamma[tid];
    bet_s[tid] = beta[tid];
    if (tid < 32) w2_s[tid] = tau_w2[hg * 32 + tid];
    if (tid < 64) bias_s[tid] = (tid < 32) ? b_in[hg * 32 + tid]
                                           : tau_b1[hg * 32 + tid - 32];
    const float tb2 = tau_b2[0];
    #pragma unroll
    for (int b = 0; b < 8; b++)
        h_s[(b << 9) + sw_tid] = h0[(size_t)(bg * 8 + b) * H_ + tid];

    // ---- x-GEMM weights -> SMEM (swizzled float4 slots) ----
    {
        int jj = tid >> 3;                          // 0..63
        const float* src = (jj < 32)
            ? (W_in + (size_t)(hg * 32 + jj) * I_)
            : (tau_w1 + (size_t)(hg * 32 + jj - 32) * (I_ + H_));
        float* dst = w_s + jj * 256;
        #pragma unroll
        for (int i = 0; i < 8; i++) {
            int slot = (tid & 7) * 8 + i;
            *(float4*)(dst + sw64(slot) * 4) = *(const float4*)(src + slot * 4);
        }
    }
    // ---- stage x(0), x(1) into x_s ----
    {
        int row = tid >> 6, slot = tid & 63;
        #pragma unroll
        for (int tt = 0; tt < 2; tt++) {
            float4 v = *(const float4*)(x + ((size_t)(bg * 8 + row) * S_ + tt) * I_
                                          + slot * 4);
            *(float4*)(x_s + (tt * 8 + row) * 256 + sw64(slot) * 4) = v;
        }
    }
    __syncthreads();

    // ---- x-GEMM: A/C tile for step tt from x_s[buf] -> pa_s/pc_s[buf] ----
    auto xgemm = [&](int buf) {
        const int wrow = (is_rec ? 0 : 32) + jlb;
        ulonglong2 wv[4][2];
        #pragma unroll
        for (int op = 0; op < 4; op++) {
            const float* wr = w_s + (wrow + op) * 256;
            wv[op][0] = *(const ulonglong2*)(wr + xs0 * 4);
            wv[op][1] = *(const ulonglong2*)(wr + xs1 * 4);
        }
        #pragma unroll
        for (int hb = 0; hb < 2; hb++) {
            unsigned long long acc2[16];
            #pragma unroll
            for (int i = 0; i < 16; i++) acc2[i] = 0ULL;
            #pragma unroll
            for (int b4 = 0; b4 < 4; b4++) {
                const float* xp = x_s + (buf * 8 + hb * 4 + b4) * 256;
                ulonglong2 xv0 = *(const ulonglong2*)(xp + xs0 * 4);
                ulonglong2 xv1 = *(const ulonglong2*)(xp + xs1 * 4);
                #pragma unroll
                for (int op = 0; op < 4; op++) {
                    FMA2(acc2[op * 4 + b4], xv0.x, wv[op][0].x);
                    FMA2(acc2[op * 4 + b4], xv0.y, wv[op][0].y);
                    FMA2(acc2[op * 4 + b4], xv1.x, wv[op][1].x);
                    FMA2(acc2[op * 4 + b4], xv1.y, wv[op][1].y);
                }
            }
            float r[16];
            #pragma unroll
            for (int i = 0; i < 16; i++) r[i] = fold2(acc2[i]);
            float r0 = butterfly16(r, lane);
            if (!(lane & 1)) {
                int idx = (lane >> 1) & 15;
                int op = idx >> 2, b4 = idx & 3;
                int b = hb * 4 + b4, jl = jlb + op;
                float v = r0 + bias_s[(is_rec ? 0 : 32) + jl];
                if (is_rec) pa_s[buf][b][jl] = v;
                else        pc_s[buf][b][jl] = v;
            }
        }
    };

    xgemm(0);
    xgemm(1);
    __syncthreads();

    const float gam = gam_s[tid], bet = bet_s[tid];

    for (int t = 0; t < S_; t++) {
        const int par = t & 1;
        const bool hasx = (t + 2 < S_);

        // prefetch x(t+2) into registers (global latency hidden under GEMV)
        float4 x4 = make_float4(0.f, 0.f, 0.f, 0.f);
        const int xrow = tid >> 6, xslot = tid & 63;
        if (hasx)
            x4 = *(const float4*)(x + ((size_t)(bg * 8 + xrow) * S_ + (t + 2)) * I_
                                    + xslot * 4);

        // ---- GEMV: 4 outputs/warp, 16 k per lane, fp32x2 ----
        #pragma unroll
        for (int hb = 0; hb < 2; hb++) {
            unsigned long long acc2[16];
            #pragma unroll
            for (int i = 0; i < 16; i++) acc2[i] = 0ULL;
            #pragma unroll
            for (int b4 = 0; b4 < 4; b4++) {
                const float* hp = h_s + ((hb * 4 + b4) << 9);
                #pragma unroll
                for (int p4 = 0; p4 < 4; p4++) {
                    ulonglong2 hv = *(const ulonglong2*)(hp + hoff[p4]);
                    #pragma unroll
                    for (int op = 0; op < 4; op++) {
                        FMA2(acc2[op * 4 + b4], hv.x, w2r[op * 8 + p4 * 2]);
                        FMA2(acc2[op * 4 + b4], hv.y, w2r[op * 8 + p4 * 2 + 1]);
                    }
                }
            }
            float r[16];
            #pragma unroll
            for (int i = 0; i < 16; i++) r[i] = fold2(acc2[i]);
            float r0 = butterfly16(r, lane);
            if (!(lane & 1)) {
                int idx = (lane >> 1) & 15;
                int op = idx >> 2, b4 = idx & 3;
                int b = hb * 4 + b4, jl = jlb + op;
                float add = is_rec ? pa_s[par][b][jl] : pc_s[par][b][jl];
                val_s[b][(is_rec ? 0 : 32) + jl] = tanh_f(r0 + add);
            }
        }
        __syncthreads();

        // stage x(t+2) into x_s[par] (x(t) there is dead since step t-2)
        if (hasx)
            *(float4*)(x_s + (par * 8 + xrow) * 256 + sw64(xslot) * 4) = x4;

        // publish f slice (warps 0-7) IN PARALLEL with partials (warps 8-15)
        if (tid < 256) {
            int b = tid >> 5, jj = tid & 31;
            g_f[par][bg * 8 + b][hg * 32 + jj] = val_s[b][jj];
        } else {
            int b = warp - 8;
            float f  = val_s[b][lane];
            float th = val_s[b][lane + 32];
            float h  = h_s[(b << 9) + sw_j];
            float p0 = f, p1 = f * f, p2 = h * f;
            float p3 = th * w2_s[lane], p4 = h, p5 = h * h;
            #pragma unroll
            for (int off = 16; off; off >>= 1) {
                p0 += __shfl_down_sync(0xffffffffu, p0, off);
                p1 += __shfl_down_sync(0xffffffffu, p1, off);
                p2 += __shfl_down_sync(0xffffffffu, p2, off);
                p3 += __shfl_down_sync(0xffffffffu, p3, off);
                p4 += __shfl_down_sync(0xffffffffu, p4, off);
                p5 += __shfl_down_sync(0xffffffffu, p5, off);
            }
            if (lane == 0) {
                g_part4[par][bg * 8 + b][hg][0] = make_float4(p0, p1, p2, p3);
                g_part4[par][bg * 8 + b][hg][1] = make_float4(p4, p5, 0.f, 0.f);
            }
        }
        __syncthreads();                 // publishes + x_s stage complete

        // ---- barrier ARRIVE (release, returns prev -> self-consistent target)
        unsigned long long prev = 0;
        if (tid == 0)
            asm volatile("atom.release.gpu.add.u64 %0, [%1], %2;"
                         : "=l"(prev) : "l"(&g_tickets), "l"(1ULL) : "memory");

        // ---- FILLER: compute A/C(t+2) while peers finish this step ----
        if (hasx) xgemm(par);

        // ---- barrier WAIT (usually satisfied already) ----
        if (tid == 0) {
            unsigned long long tgt = (prev & ~127ULL) + 128ULL;
            unsigned long long cur;
            do {
                asm volatile("ld.acquire.gpu.u64 %0, [%1];"
                             : "=l"(cur) : "l"(&g_tickets) : "memory");
            } while (cur < tgt);
        }
        __syncthreads();

        // ---- hoisted loads: partials first, then all f rows (overlap L2) ----
        float4 u  = make_float4(0.f, 0.f, 0.f, 0.f);
        float4 v4 = make_float4(0.f, 0.f, 0.f, 0.f);
        if (warp < 8 && lane < 16) {
            u  = __ldcg(&g_part4[par][bg * 8 + warp][lane][0]);
            v4 = __ldcg(&g_part4[par][bg * 8 + warp][lane][1]);
        }
        float f_r[8];
        #pragma unroll
        for (int b = 0; b < 8; b++)
            f_r[b] = __ldcg(&g_f[par][bg * 8 + b][tid]);

        // ---- row stats (data in lanes 0-15 -> tree starts at off=8) ----
        if (warp < 8) {
            float s0 = u.x, s1 = u.y, s2 = u.z, s3r = u.w, s4 = v4.x, s5 = v4.y;
            #pragma unroll
            for (int off = 8; off; off >>= 1) {
                s0  += __shfl_down_sync(0xffffffffu, s0, off);
                s1  += __shfl_down_sync(0xffffffffu, s1, off);
                s2  += __shfl_down_sync(0xffffffffu, s2, off);
                s3r += __shfl_down_sync(0xffffffffu, s3r, off);
                s4  += __shfl_down_sync(0xffffffffu, s4, off);
                s5  += __shfl_down_sync(0xffffffffu, s5, off);
            }
            if (lane == 0) {
                int bG = bg * 8 + warp;
                float tau  = 1.f + 9.f / (1.f + __expf(-(s3r + tb2)));
                float cc   = 0.1f / tau;
                float aa   = 1.f - cc;
                float mean = (aa * s4 + cc * s0) * (1.f / 512.f);
                float ep2  = (aa * aa * s5 + 2.f * aa * cc * s2 + cc * cc * s1)
                             * (1.f / 512.f);
                float rstd = rsqrtf(ep2 - mean * mean + 1e-5f);
                stats_s[warp] = make_float4(aa, cc, mean, rstd);
                if (hg == 0) tauh[(size_t)bG * S_ + t] = tau;
            }
        }
        __syncthreads();

        // ---- reconstruct full h_new rows; write own output slice ----
        #pragma unroll
        for (int b = 0; b < 8; b++) {
            float4 st = stats_s[b];
            float h = h_s[(b << 9) + sw_tid];
            float p  = st.x * h + st.y * f_r[b];
            float hn = (p - st.z) * st.w * gam + bet;
            h_s[(b << 9) + sw_tid] = hn;
            if ((tid >> 5) == hg) {
                out[((size_t)(bg * 8 + b) * S_ + t) * H_ + tid] = hn;
                if (t == S_ - 1) hfin[(size_t)(bg * 8 + b) * H_ + tid] = hn;
            }
        }
        __syncthreads();   // h_s reuse ordering for next step
    }
}

// =============================================================================
extern "C" void kernel_launch(void* const* d_in, const int* in_sizes, int n_in,
                              void* d_out, int out_size)
{
    const float* x     = (const float*)d_in[0];
    const float* h0    = (const float*)d_in[1];
    const float* W_in  = (const float*)d_in[2];
    const float* b_in  = (const float*)d_in[3];
    const float* W_rec = (const float*)d_in[4];
    const float* tw1   = (const float*)d_in[5];
    const float* tb1   = (const float*)d_in[6];
    const float* tw2   = (const float*)d_in[7];
    const float* tb2   = (const float*)d_in[8];
    const float* gamma = (const float*)d_in[9];
    const float* beta  = (const float*)d_in[10];

    float* out  = (float*)d_out;                       // [B, S, H]
    float* hfin = out + (size_t)B_ * S_ * H_;          // [B, H]
    float* tauh = hfin + (size_t)B_ * H_;              // [B, S, 1]

    cudaFuncSetAttribute(liquid_recurrent,
                         cudaFuncAttributeMaxDynamicSharedMemorySize, SMEM_TOT);
    liquid_recurrent<<<NC, 512, SMEM_TOT>>>(x, h0, W_in, b_in, W_rec, tw1, tb1,
                                            tw2, tb2, gamma, beta,
                                            out, hfin, tauh);
}

// round 13
// speedup vs baseline: 1.0290x; 1.0290x over previous
#include <cuda_runtime.h>
#include <cstdint>

#define S_  1024
#define B_  64
#define I_  256
#define H_  512
#define NC  128      // persistent CTAs (16 h-groups x 8 b-groups)
#define NHG 16

// ---------------- scratch (static __device__ — no allocation) ----------------
__device__ float  g_f[2][B_][H_];                 // tanh(u) exchange, double-buffered
__device__ float4 g_part4[2][B_][NHG][2];         // 6 partial sums per (b, hgroup)
__device__ unsigned long long g_tickets;          // barrier arrivals (monotonic u64)

// ---- packed fp32x2 helpers (Blackwell dual-issue fp32) ----
#define FMA2(d, a, b) \
    asm("fma.rn.f32x2 %0, %1, %2, %0;" : "+l"(d) : "l"(a), "l"(b))

#define BAR_ARRIVE(id, cnt) \
    asm volatile("bar.arrive %0, %1;" :: "r"(id), "r"(cnt) : "memory")
#define BAR_SYNC(id, cnt) \
    asm volatile("bar.sync %0, %1;"   :: "r"(id), "r"(cnt) : "memory")

__device__ __forceinline__ unsigned long long pk2(float a, float b) {
    return (unsigned long long)__float_as_uint(a) |
           ((unsigned long long)__float_as_uint(b) << 32);
}
__device__ __forceinline__ float fold2(unsigned long long v) {
    return __uint_as_float((unsigned)v) + __uint_as_float((unsigned)(v >> 32));
}
// XOR swizzle on a 512-float h row (16B granularity) -> conflict-free LDS.128
__device__ __forceinline__ int hswz(int f) {
    int u = f >> 2;
    u ^= (u >> 3) & 7;
    return (u << 2) | (f & 3);
}
// XOR swizzle on 64 float4-slots of a 256-float row (involution)
__device__ __forceinline__ int sw64(int s) { return s ^ ((s >> 3) & 7); }

// fast tanh: (1 - e^{-2|x|}) / (1 + e^{-2|x|}), sign-restored (~1e-6 abs err)
__device__ __forceinline__ float tanh_f(float x) {
    float e = __expf(-2.f * fabsf(x));
    float t = __fdividef(1.f - e, 1.f + e);
    return copysignf(t, x);
}

// 16-value butterfly reduce over 32 lanes; result valid on even lanes,
// value index = (lane>>1)&15 (idx = op*4 + b4).
__device__ __forceinline__ float butterfly16(float r[16], int lane) {
    int up = lane & 16;
    #pragma unroll
    for (int i = 0; i < 8; i++) {
        float snd = up ? r[i] : r[i + 8];
        float kp  = up ? r[i + 8] : r[i];
        r[i] = kp + __shfl_xor_sync(0xffffffffu, snd, 16);
    }
    up = lane & 8;
    #pragma unroll
    for (int i = 0; i < 4; i++) {
        float snd = up ? r[i] : r[i + 4];
        float kp  = up ? r[i + 4] : r[i];
        r[i] = kp + __shfl_xor_sync(0xffffffffu, snd, 8);
    }
    up = lane & 4;
    #pragma unroll
    for (int i = 0; i < 2; i++) {
        float snd = up ? r[i] : r[i + 2];
        float kp  = up ? r[i + 2] : r[i];
        r[i] = kp + __shfl_xor_sync(0xffffffffu, snd, 4);
    }
    {
        int u2 = lane & 2;
        float snd = u2 ? r[0] : r[1];
        float kp  = u2 ? r[1] : r[0];
        r[0] = kp + __shfl_xor_sync(0xffffffffu, snd, 2);
    }
    r[0] += __shfl_xor_sync(0xffffffffu, r[0], 1);
    return r[0];
}

// ---------------- dynamic SMEM layout (bytes) ----------------
#define OFF_H     0          // h_s      : 8 x 512 f                (16384)
#define OFF_X     16384      // x_s      : 8 x 256 f                (8192)
#define OFF_W     24576      // w_s      : 64 x 256 f               (65536)
#define OFF_PA    90112      // pa_s     : 2 x 8 x 32 f             (2048)
#define OFF_PC    92160      // pc_s     : 2 x 8 x 32 f             (2048)
#define OFF_VAL   94208      // val_s    : 8 x 64 f                 (2048)
#define OFF_GAM   96256      // gam_s    : 512 f                    (2048)
#define OFF_BET   98304      // bet_s    : 512 f                    (2048)
#define OFF_ST    100352     // stats_s  : 8 float4                 (128)
#define OFF_W2    100480     // w2_s     : 32 f                     (128)
#define OFF_BIAS  100608     // bias_s   : 64 f                     (256)
#define SMEM_TOT  100864

// =============================================================================
// Single persistent kernel: recurrent scan with the input-GEMM computed by
// warps 8-15 INSIDE the post-barrier phase (warp-specialized filler).
// =============================================================================
__global__ __launch_bounds__(512, 1) void liquid_recurrent(
    const float* __restrict__ x,      const float* __restrict__ h0,
    const float* __restrict__ W_in,   const float* __restrict__ b_in,
    const float* __restrict__ W_rec,  const float* __restrict__ tau_w1,
    const float* __restrict__ tau_b1, const float* __restrict__ tau_w2,
    const float* __restrict__ tau_b2, const float* __restrict__ gamma,
    const float* __restrict__ beta,
    float* __restrict__ out, float* __restrict__ hfin, float* __restrict__ tauh)
{
    extern __shared__ __align__(16) char smem[];
    float* h_s   = (float*)(smem + OFF_H);
    float* x_s   = (float*)(smem + OFF_X);
    float* w_s   = (float*)(smem + OFF_W);
    float (*pa_s)[8][32] = (float(*)[8][32])(smem + OFF_PA);
    float (*pc_s)[8][32] = (float(*)[8][32])(smem + OFF_PC);
    float (*val_s)[64]   = (float(*)[64])(smem + OFF_VAL);
    float* gam_s = (float*)(smem + OFF_GAM);
    float* bet_s = (float*)(smem + OFF_BET);
    float4* stats_s = (float4*)(smem + OFF_ST);
    float* w2_s  = (float*)(smem + OFF_W2);
    float* bias_s = (float*)(smem + OFF_BIAS);

    const int tid  = threadIdx.x;
    const int hg   = blockIdx.x & 15;
    const int bg   = blockIdx.x >> 4;
    const int warp = tid >> 5, lane = tid & 31;
    const bool is_rec = (warp < 8);
    const int jlb  = (warp & 7) * 4;                // jl base for this warp

    // ---- recurrent weights -> registers as f32x2 k-pairs (64 regs) ----
    unsigned long long w2r[32];
    {
        #pragma unroll
        for (int op = 0; op < 4; op++) {
            int j = hg * 32 + jlb + op;
            const float* wr = is_rec ? (W_rec + (size_t)j * H_)
                                     : (tau_w1 + (size_t)j * (I_ + H_) + I_);
            #pragma unroll
            for (int p4 = 0; p4 < 4; p4++) {
                float4 v = *(const float4*)(wr + lane * 16 + p4 * 4);
                w2r[op * 8 + p4 * 2]     = pk2(v.x, v.y);
                w2r[op * 8 + p4 * 2 + 1] = pk2(v.z, v.w);
            }
        }
    }
    const int s3 = (lane >> 1) & 7;
    int hoff[4];
    #pragma unroll
    for (int p4 = 0; p4 < 4; p4++) hoff[p4] = ((lane * 4 + p4) ^ s3) << 2;
    const int sw_tid = hswz(tid);
    const int sw_j   = hswz(hg * 32 + lane);
    const int xs0 = sw64(lane * 2);                 // physical slot of logical 2*lane
    const int xs1 = xs0 ^ 1;                        // physical slot of logical 2*lane+1

    gam_s[tid] = gamma[tid];
    bet_s[tid] = beta[tid];
    if (tid < 32) w2_s[tid] = tau_w2[hg * 32 + tid];
    if (tid < 64) bias_s[tid] = (tid < 32) ? b_in[hg * 32 + tid]
                                           : tau_b1[hg * 32 + tid - 32];
    const float tb2 = tau_b2[0];
    #pragma unroll
    for (int b = 0; b < 8; b++)
        h_s[(b << 9) + sw_tid] = h0[(size_t)(bg * 8 + b) * H_ + tid];

    // ---- x-GEMM weights -> SMEM (swizzled float4 slots) ----
    {
        int jj = tid >> 3;                          // 0..63
        const float* src = (jj < 32)
            ? (W_in + (size_t)(hg * 32 + jj) * I_)
            : (tau_w1 + (size_t)(hg * 32 + jj - 32) * (I_ + H_));
        float* dst = w_s + jj * 256;
        #pragma unroll
        for (int i = 0; i < 8; i++) {
            int slot = (tid & 7) * 8 + i;
            *(float4*)(dst + sw64(slot) * 4) = *(const float4*)(src + slot * 4);
        }
    }
    // ---- stage x(0) into x_s ----
    {
        int row = tid >> 6, slot = tid & 63;
        float4 v = *(const float4*)(x + ((size_t)(bg * 8 + row) * S_) * I_
                                      + slot * 4);
        *(float4*)(x_s + row * 256 + sw64(slot) * 4) = v;
    }
    __syncthreads();

    // ---- x-GEMM (one role): A or C tile from x_s -> pa_s/pc_s[p] ----
    auto xgemm_role = [&](int p, bool rec_role, int jl_base) {
        const int wrow = (rec_role ? 0 : 32) + jl_base;
        ulonglong2 wv[4][2];
        #pragma unroll
        for (int op = 0; op < 4; op++) {
            const float* wr = w_s + (wrow + op) * 256;
            wv[op][0] = *(const ulonglong2*)(wr + xs0 * 4);
            wv[op][1] = *(const ulonglong2*)(wr + xs1 * 4);
        }
        #pragma unroll
        for (int hb = 0; hb < 2; hb++) {
            unsigned long long acc2[16];
            #pragma unroll
            for (int i = 0; i < 16; i++) acc2[i] = 0ULL;
            #pragma unroll
            for (int b4 = 0; b4 < 4; b4++) {
                const float* xp = x_s + (hb * 4 + b4) * 256;
                ulonglong2 xv0 = *(const ulonglong2*)(xp + xs0 * 4);
                ulonglong2 xv1 = *(const ulonglong2*)(xp + xs1 * 4);
                #pragma unroll
                for (int op = 0; op < 4; op++) {
                    FMA2(acc2[op * 4 + b4], xv0.x, wv[op][0].x);
                    FMA2(acc2[op * 4 + b4], xv0.y, wv[op][0].y);
                    FMA2(acc2[op * 4 + b4], xv1.x, wv[op][1].x);
                    FMA2(acc2[op * 4 + b4], xv1.y, wv[op][1].y);
                }
            }
            float r[16];
            #pragma unroll
            for (int i = 0; i < 16; i++) r[i] = fold2(acc2[i]);
            float r0 = butterfly16(r, lane);
            if (!(lane & 1)) {
                int idx = (lane >> 1) & 15;
                int op = idx >> 2, b4 = idx & 3;
                int b = hb * 4 + b4, jl = jl_base + op;
                float v = r0 + bias_s[(rec_role ? 0 : 32) + jl];
                if (rec_role) pa_s[p][b][jl] = v;
                else          pc_s[p][b][jl] = v;
            }
        }
    };

    // prologue: A/C(0) -> pa_s/pc_s[0], each warp its own role (fast)
    xgemm_role(0, is_rec, jlb);
    __syncthreads();

    const float gam = gam_s[tid], bet = bet_s[tid];

    for (int t = 0; t < S_; t++) {
        const int par = t & 1;
        const int p1  = par ^ 1;
        const bool hasx = (t + 1 < S_);

        // prefetch x(t+1) into registers (global latency hidden under GEMV)
        float4 x4 = make_float4(0.f, 0.f, 0.f, 0.f);
        const int xrow = tid >> 6, xslot = tid & 63;
        if (hasx)
            x4 = *(const float4*)(x + ((size_t)(bg * 8 + xrow) * S_ + (t + 1)) * I_
                                    + xslot * 4);

        // ---- GEMV: 4 outputs/warp, 16 k per lane, fp32x2 ----
        #pragma unroll
        for (int hb = 0; hb < 2; hb++) {
            unsigned long long acc2[16];
            #pragma unroll
            for (int i = 0; i < 16; i++) acc2[i] = 0ULL;
            #pragma unroll
            for (int b4 = 0; b4 < 4; b4++) {
                const float* hp = h_s + ((hb * 4 + b4) << 9);
                #pragma unroll
                for (int p4 = 0; p4 < 4; p4++) {
                    ulonglong2 hv = *(const ulonglong2*)(hp + hoff[p4]);
                    #pragma unroll
                    for (int op = 0; op < 4; op++) {
                        FMA2(acc2[op * 4 + b4], hv.x, w2r[op * 8 + p4 * 2]);
                        FMA2(acc2[op * 4 + b4], hv.y, w2r[op * 8 + p4 * 2 + 1]);
                    }
                }
            }
            float r[16];
            #pragma unroll
            for (int i = 0; i < 16; i++) r[i] = fold2(acc2[i]);
            float r0 = butterfly16(r, lane);
            if (!(lane & 1)) {
                int idx = (lane >> 1) & 15;
                int op = idx >> 2, b4 = idx & 3;
                int b = hb * 4 + b4, jl = jlb + op;
                float add = is_rec ? pa_s[par][b][jl] : pc_s[par][b][jl];
                val_s[b][(is_rec ? 0 : 32) + jl] = tanh_f(r0 + add);
            }
        }
        __syncthreads();                    // val_s ready; x_s(t) consumed

        // stage x(t+1) into x_s (read later this step by filler warps)
        if (hasx)
            *(float4*)(x_s + xrow * 256 + sw64(xslot) * 4) = x4;

        // publish f slice (warps 0-7) IN PARALLEL with partials (warps 8-15)
        if (tid < 256) {
            int b = tid >> 5, jj = tid & 31;
            g_f[par][bg * 8 + b][hg * 32 + jj] = val_s[b][jj];
        } else {
            int b = warp - 8;
            float f  = val_s[b][lane];
            float th = val_s[b][lane + 32];
            float h  = h_s[(b << 9) + sw_j];
            float p0 = f, p1v = f * f, p2 = h * f;
            float p3 = th * w2_s[lane], p4 = h, p5 = h * h;
            #pragma unroll
            for (int off = 16; off; off >>= 1) {
                p0  += __shfl_down_sync(0xffffffffu, p0, off);
                p1v += __shfl_down_sync(0xffffffffu, p1v, off);
                p2  += __shfl_down_sync(0xffffffffu, p2, off);
                p3  += __shfl_down_sync(0xffffffffu, p3, off);
                p4  += __shfl_down_sync(0xffffffffu, p4, off);
                p5  += __shfl_down_sync(0xffffffffu, p5, off);
            }
            if (lane == 0) {
                g_part4[par][bg * 8 + b][hg][0] = make_float4(p0, p1v, p2, p3);
                g_part4[par][bg * 8 + b][hg][1] = make_float4(p4, p5, 0.f, 0.f);
            }
        }
        __syncthreads();                    // publishes + x_s stage complete

        // ---- barrier ARRIVE (tid0) ----
        if (tid == 0) {
            unsigned long long prev;
            asm volatile("atom.release.gpu.add.u64 %0, [%1], %2;"
                         : "=l"(prev) : "l"(&g_tickets), "l"(1ULL) : "memory");
            unsigned long long tgt = (prev & ~127ULL) + 128ULL;
            unsigned long long cur;
            do {
                asm volatile("ld.acquire.gpu.u64 %0, [%1];"
                             : "=l"(cur) : "l"(&g_tickets) : "memory");
            } while (cur < tgt);
        }

        float f_r[8];
        float4 u  = make_float4(0.f, 0.f, 0.f, 0.f);
        float4 v4 = make_float4(0.f, 0.f, 0.f, 0.f);

        if (warp >= 8) {
            // ---- FILLER: A/C(t+1) while warps 0-7 run the stats chain ----
            if (hasx) {
                xgemm_role(p1, true,  jlb);
                xgemm_role(p1, false, jlb);
            }
            BAR_SYNC(2, 288);               // barrier-done guarantee (warp0 arrived)
            #pragma unroll
            for (int b = 0; b < 8; b++)
                f_r[b] = __ldcg(&g_f[par][bg * 8 + b][tid]);
        } else {
            if (warp == 0) BAR_ARRIVE(2, 288);   // after tid0's poll (reconverged)
            BAR_SYNC(1, 256);               // warps 0-7 gate on barrier-done
            if (lane < 16) {
                u  = __ldcg(&g_part4[par][bg * 8 + warp][lane][0]);
                v4 = __ldcg(&g_part4[par][bg * 8 + warp][lane][1]);
            }
            #pragma unroll
            for (int b = 0; b < 8; b++)
                f_r[b] = __ldcg(&g_f[par][bg * 8 + b][tid]);

            // ---- row stats (data in lanes 0-15 -> tree starts at off=8) ----
            float s0 = u.x, s1 = u.y, s2 = u.z, s3r = u.w, s4 = v4.x, s5 = v4.y;
            #pragma unroll
            for (int off = 8; off; off >>= 1) {
                s0  += __shfl_down_sync(0xffffffffu, s0, off);
                s1  += __shfl_down_sync(0xffffffffu, s1, off);
                s2  += __shfl_down_sync(0xffffffffu, s2, off);
                s3r += __shfl_down_sync(0xffffffffu, s3r, off);
                s4  += __shfl_down_sync(0xffffffffu, s4, off);
                s5  += __shfl_down_sync(0xffffffffu, s5, off);
            }
            if (lane == 0) {
                int bG = bg * 8 + warp;
                float tau  = 1.f + 9.f / (1.f + __expf(-(s3r + tb2)));
                float cc   = 0.1f / tau;
                float aa   = 1.f - cc;
                float mean = (aa * s4 + cc * s0) * (1.f / 512.f);
                float ep2  = (aa * aa * s5 + 2.f * aa * cc * s2 + cc * cc * s1)
                             * (1.f / 512.f);
                float rstd = rsqrtf(ep2 - mean * mean + 1e-5f);
                stats_s[warp] = make_float4(aa, cc, mean, rstd);
                if (hg == 0) tauh[(size_t)bG * S_ + t] = tau;
            }
        }
        __syncthreads();                    // stats_s + filler tiles + f loads

        // ---- reconstruct full h_new rows; write own output slice ----
        #pragma unroll
        for (int b = 0; b < 8; b++) {
            float4 st = stats_s[b];
            float h = h_s[(b << 9) + sw_tid];
            float p  = st.x * h + st.y * f_r[b];
            float hn = (p - st.z) * st.w * gam + bet;
            h_s[(b << 9) + sw_tid] = hn;
            if ((tid >> 5) == hg) {
                out[((size_t)(bg * 8 + b) * S_ + t) * H_ + tid] = hn;
                if (t == S_ - 1) hfin[(size_t)(bg * 8 + b) * H_ + tid] = hn;
            }
        }
        __syncthreads();                    // h_s reuse ordering for next step
    }
}

// =============================================================================
extern "C" void kernel_launch(void* const* d_in, const int* in_sizes, int n_in,
                              void* d_out, int out_size)
{
    const float* x     = (const float*)d_in[0];
    const float* h0    = (const float*)d_in[1];
    const float* W_in  = (const float*)d_in[2];
    const float* b_in  = (const float*)d_in[3];
    const float* W_rec = (const float*)d_in[4];
    const float* tw1   = (const float*)d_in[5];
    const float* tb1   = (const float*)d_in[6];
    const float* tw2   = (const float*)d_in[7];
    const float* tb2   = (const float*)d_in[8];
    const float* gamma = (const float*)d_in[9];
    const float* beta  = (const float*)d_in[10];

    float* out  = (float*)d_out;                       // [B, S, H]
    float* hfin = out + (size_t)B_ * S_ * H_;          // [B, H]
    float* tauh = hfin + (size_t)B_ * H_;              // [B, S, 1]

    cudaFuncSetAttribute(liquid_recurrent,
                         cudaFuncAttributeMaxDynamicSharedMemorySize, SMEM_TOT);
    liquid_recurrent<<<NC, 512, SMEM_TOT>>>(x, h0, W_in, b_in, W_rec, tw1, tb1,
                                            tw2, tb2, gamma, beta,
                                            out, hfin, tauh);
}

// round 14
// speedup vs baseline: 1.1031x; 1.0720x over previous
#include <cuda_runtime.h>
#include <cstdint>

#define S_  1024
#define B_  64
#define I_  256
#define H_  512
#define NC  128      // persistent CTAs (16 h-groups x 8 b-groups)
#define NHG 16

// ---------------- scratch (static __device__ — no allocation) ----------------
__device__ float  g_A[(size_t)S_ * B_ * H_];      // x @ W_in.T + b_in      [t*64+b][j]
__device__ float  g_C[(size_t)S_ * B_ * H_];      // x @ tau_w1[:,:I].T+b1  [t*64+b][j]
__device__ float  g_f[2][B_][H_];                 // tanh(u) exchange, double-buffered
__device__ float4 g_part4[2][B_][NHG][2];         // 6 partial sums per (b, hgroup)
__device__ unsigned long long g_tickets;          // barrier arrivals (monotonic u64)

// ---- packed fp32x2 helpers (Blackwell dual-issue fp32) ----
#define FMA2(d, a, b) \
    asm("fma.rn.f32x2 %0, %1, %2, %0;" : "+l"(d) : "l"(a), "l"(b))

__device__ __forceinline__ unsigned long long pk2(float a, float b) {
    return (unsigned long long)__float_as_uint(a) |
           ((unsigned long long)__float_as_uint(b) << 32);
}
__device__ __forceinline__ float fold2(unsigned long long v) {
    return __uint_as_float((unsigned)v) + __uint_as_float((unsigned)(v >> 32));
}
// XOR swizzle on a 512-float h row (16B granularity) -> conflict-free LDS.128
__device__ __forceinline__ int hswz(int f) {
    int u = f >> 2;
    u ^= (u >> 3) & 7;
    return (u << 2) | (f & 3);
}
// fast tanh: (1 - e^{-2|x|}) / (1 + e^{-2|x|}), sign-restored (~1e-6 abs err)
__device__ __forceinline__ float tanh_f(float x) {
    float e = __expf(-2.f * fabsf(x));
    float t = __fdividef(1.f - e, 1.f + e);
    return copysignf(t, x);
}
__device__ __forceinline__ unsigned f2tf32(float f) {
    unsigned u;
    asm("cvt.rna.tf32.f32 %0, %1;" : "=r"(u) : "f"(f));
    return u;
}

// =============================================================================
// Kernel 1: time-parallel precompute GEMM on TENSOR CORES (tf32 mma.sync).
//   out[r, n] = sum_k x_row(r)[k] * W'(n)[k] + bias(n), r in [0,65536), n [0,1024)
//   CTA tile: BM=128 (r), BN=128 (n), K=256 in two 128-chunks. 256 threads.
//   SMEM rows use a PAIRED k layout: within each k8 block, position 2c holds
//   logical k=c and 2c+1 holds k=c+4 -> every mma fragment is one LDS.64.
// =============================================================================
#define GROW 132                          // padded row stride (floats/uints)
#define GSM  (2 * 128 * GROW * 4)         // xs + ws

__global__ __launch_bounds__(256) void precompute_gemm_tf32(
    const float* __restrict__ x, const float* __restrict__ W_in,
    const float* __restrict__ b_in, const float* __restrict__ tau_w1,
    const float* __restrict__ tau_b1)
{
    extern __shared__ __align__(16) unsigned gsm[];
    unsigned* xs = gsm;                   // [128][GROW]
    unsigned* ws = gsm + 128 * GROW;      // [128][GROW]

    const int tid   = threadIdx.x;
    const int mtile = blockIdx.x;         // 0..511  (128 r each)
    const int nbase = blockIdx.y * 128;   // 0..896
    const int warp  = tid >> 5, lane = tid & 31;
    const int gid   = lane >> 2, tig = lane & 3;
    const int wm    = warp & 3;           // m-quadrant (32 rows)
    const int wn    = warp >> 2;          // n-half (64 cols)

    float acc[2][8][4];
    #pragma unroll
    for (int mt = 0; mt < 2; mt++)
        #pragma unroll
        for (int nt = 0; nt < 8; nt++)
            #pragma unroll
            for (int c = 0; c < 4; c++) acc[mt][nt][c] = 0.f;

    const int srow = tid >> 1;            // staging row 0..127
    const int shalf = tid & 1;            // k-half of the chunk

    for (int kc = 0; kc < 2; kc++) {
        // ---- stage x chunk (tf32-converted, paired layout) ----
        {
            int r = mtile * 128 + srow;
            int t = r >> 6, b = r & 63;
            const float* src = x + ((size_t)b * S_ + t) * I_ + kc * 128 + shalf * 64;
            unsigned* dst = xs + srow * GROW;
            #pragma unroll
            for (int i = 0; i < 16; i++) {
                int k0 = shalf * 64 + i * 4;
                float4 v = *(const float4*)(src + i * 4);
                int blk = k0 >> 3, odd = (k0 >> 2) & 1;
                int p = blk * 8 + odd;
                dst[p]     = f2tf32(v.x);
                dst[p + 2] = f2tf32(v.y);
                dst[p + 4] = f2tf32(v.z);
                dst[p + 6] = f2tf32(v.w);
            }
        }
        // ---- stage weights chunk ----
        {
            int ng = nbase + srow;
            const float* src = (ng < 512)
                ? (W_in + (size_t)ng * I_)
                : (tau_w1 + (size_t)(ng - 512) * (I_ + H_));
            src += kc * 128 + shalf * 64;
            unsigned* dst = ws + srow * GROW;
            #pragma unroll
            for (int i = 0; i < 16; i++) {
                int k0 = shalf * 64 + i * 4;
                float4 v = *(const float4*)(src + i * 4);
                int blk = k0 >> 3, odd = (k0 >> 2) & 1;
                int p = blk * 8 + odd;
                dst[p]     = f2tf32(v.x);
                dst[p + 2] = f2tf32(v.y);
                dst[p + 4] = f2tf32(v.z);
                dst[p + 6] = f2tf32(v.w);
            }
        }
        __syncthreads();

        // ---- mma main loop: 16 k8 steps per chunk ----
        #pragma unroll 4
        for (int ks = 0; ks < 16; ks++) {
            int poff = ks * 8 + 2 * tig;
            unsigned a0[2], a1[2], a2[2], a3[2];
            #pragma unroll
            for (int mt = 0; mt < 2; mt++) {
                int row = wm * 32 + mt * 16 + gid;
                uint2 lo = *(const uint2*)(xs + row * GROW + poff);
                uint2 hi = *(const uint2*)(xs + (row + 8) * GROW + poff);
                a0[mt] = lo.x; a2[mt] = lo.y;   // (g, tig), (g, tig+4)
                a1[mt] = hi.x; a3[mt] = hi.y;   // (g+8, tig), (g+8, tig+4)
            }
            #pragma unroll
            for (int nt = 0; nt < 8; nt++) {
                int nrow = wn * 64 + nt * 8 + gid;
                uint2 bq = *(const uint2*)(ws + nrow * GROW + poff);
                #pragma unroll
                for (int mt = 0; mt < 2; mt++) {
                    asm volatile(
                        "mma.sync.aligned.m16n8k8.row.col.f32.tf32.tf32.f32 "
                        "{%0,%1,%2,%3}, {%4,%5,%6,%7}, {%8,%9}, {%0,%1,%2,%3};"
                        : "+f"(acc[mt][nt][0]), "+f"(acc[mt][nt][1]),
                          "+f"(acc[mt][nt][2]), "+f"(acc[mt][nt][3])
                        : "r"(a0[mt]), "r"(a1[mt]), "r"(a2[mt]), "r"(a3[mt]),
                          "r"(bq.x), "r"(bq.y));
                }
            }
        }
        __syncthreads();
    }

    // ---- epilogue: add bias, route to g_A / g_C ----
    #pragma unroll
    for (int nt = 0; nt < 8; nt++) {
        int ng = nbase + wn * 64 + nt * 8 + 2 * tig;           // even
        float2 bias = (ng < 512) ? *(const float2*)(b_in + ng)
                                 : *(const float2*)(tau_b1 + (ng - 512));
        #pragma unroll
        for (int mt = 0; mt < 2; mt++) {
            int r0 = mtile * 128 + wm * 32 + mt * 16 + gid;
            float2 v0 = make_float2(acc[mt][nt][0] + bias.x,
                                    acc[mt][nt][1] + bias.y);
            float2 v1 = make_float2(acc[mt][nt][2] + bias.x,
                                    acc[mt][nt][3] + bias.y);
            if (ng < 512) {
                *(float2*)(g_A + (size_t)r0 * H_ + ng)       = v0;
                *(float2*)(g_A + (size_t)(r0 + 8) * H_ + ng) = v1;
            } else {
                *(float2*)(g_C + (size_t)r0 * H_ + (ng - 512))       = v0;
                *(float2*)(g_C + (size_t)(r0 + 8) * H_ + (ng - 512)) = v1;
            }
        }
    }
}

// =============================================================================
// Kernel 2: persistent recurrent scan — EXACT champion (R9, 5286us):
//   128 CTAs x 512, single ticket barrier, register weights, fast tanh,
//   hoisted post-barrier loads. Only delta: stats tree starts at off=8
//   (partials live in lanes 0-15; off=16 round added zeros).
// =============================================================================
__device__ __forceinline__ void grid_barrier()
{
    __syncthreads();
    if (threadIdx.x == 0) {
        unsigned long long prev;
        asm volatile("atom.release.gpu.add.u64 %0, [%1], %2;"
                     : "=l"(prev) : "l"(&g_tickets), "l"(1ULL) : "memory");
        unsigned long long target = (prev & ~127ULL) + 128ULL;
        unsigned long long cur;
        do {
            asm volatile("ld.acquire.gpu.u64 %0, [%1];"
                         : "=l"(cur) : "l"(&g_tickets) : "memory");
        } while (cur < target);
    }
    __syncthreads();
}

__global__ __launch_bounds__(512, 1) void liquid_recurrent(
    const float* __restrict__ h0,     const float* __restrict__ W_rec,
    const float* __restrict__ tau_w1, const float* __restrict__ tau_w2,
    const float* __restrict__ tau_b2, const float* __restrict__ gamma,
    const float* __restrict__ beta,
    float* __restrict__ out, float* __restrict__ hfin, float* __restrict__ tauh)
{
    __shared__ __align__(16) float h_s[8 * H_];     // swizzled h rows (16 KB)
    __shared__ float  pa_s[2][8][32];               // A tiles, double-buffered
    __shared__ float  pc_s[2][8][32];               // C tiles, double-buffered
    __shared__ float  val_s[8][64];                 // f (o<32) / t_hid (o>=32)
    __shared__ float4 stats_s[8];                   // {a, c, mean, rstd}
    __shared__ float  gam_s[H_], bet_s[H_];
    __shared__ float  w2_s[32];

    const int tid  = threadIdx.x;
    const int hg   = blockIdx.x & 15;
    const int bg   = blockIdx.x >> 4;
    const int warp = tid >> 5, lane = tid & 31;
    const bool is_rec = (warp < 8);
    const int jlb  = (warp & 7) * 4;                // jl base for this warp

    // ---- recurrent weights -> registers as f32x2 k-pairs (64 regs) ----
    unsigned long long w2r[32];
    {
        #pragma unroll
        for (int op = 0; op < 4; op++) {
            int j = hg * 32 + jlb + op;
            const float* wr = is_rec ? (W_rec + (size_t)j * H_)
                                     : (tau_w1 + (size_t)j * (I_ + H_) + I_);
            #pragma unroll
            for (int p4 = 0; p4 < 4; p4++) {
                float4 v = *(const float4*)(wr + lane * 16 + p4 * 4);
                w2r[op * 8 + p4 * 2]     = pk2(v.x, v.y);
                w2r[op * 8 + p4 * 2 + 1] = pk2(v.z, v.w);
            }
        }
    }
    const int s3 = (lane >> 1) & 7;
    int hoff[4];
    #pragma unroll
    for (int p4 = 0; p4 < 4; p4++) hoff[p4] = ((lane * 4 + p4) ^ s3) << 2;
    const int sw_tid = hswz(tid);
    const int sw_j   = hswz(hg * 32 + lane);

    gam_s[tid] = gamma[tid];
    bet_s[tid] = beta[tid];
    if (tid < 32) w2_s[tid] = tau_w2[hg * 32 + tid];
    const float tb2 = tau_b2[0];
    #pragma unroll
    for (int b = 0; b < 8; b++)
        h_s[(b << 9) + sw_tid] = h0[(size_t)(bg * 8 + b) * H_ + tid];
    // prologue: tiles for t=0
    {
        int bb = (tid & 255) >> 5, jj = tid & 31;
        size_t base = ((size_t)(bg * 8 + bb)) * H_ + hg * 32 + jj;
        if (tid < 256) pa_s[0][bb][jj] = g_A[base];
        else           pc_s[0][bb][jj] = g_C[base];
    }
    __syncthreads();

    const float gam = gam_s[tid], bet = bet_s[tid];

    for (int t = 0; t < S_; t++) {
        const int par = t & 1;

        // prefetch next step's A/C tile into registers (DRAM latency hidden)
        float pf = 0.f;
        const int pt = t + 1;
        const int pbb = (tid & 255) >> 5, pjj = tid & 31;
        if (pt < S_) {
            size_t base = ((size_t)pt * B_ + bg * 8 + pbb) * H_ + hg * 32 + pjj;
            pf = (tid < 256) ? g_A[base] : g_C[base];
        }

        // ---- GEMV: 4 outputs/warp, 16 k per lane, fp32x2 ----
        #pragma unroll
        for (int hb = 0; hb < 2; hb++) {
            unsigned long long acc2[16];
            #pragma unroll
            for (int i = 0; i < 16; i++) acc2[i] = 0ULL;
            #pragma unroll
            for (int b4 = 0; b4 < 4; b4++) {
                const float* hp = h_s + ((hb * 4 + b4) << 9);
                #pragma unroll
                for (int p4 = 0; p4 < 4; p4++) {
                    ulonglong2 hv = *(const ulonglong2*)(hp + hoff[p4]);
                    #pragma unroll
                    for (int op = 0; op < 4; op++) {
                        FMA2(acc2[op * 4 + b4], hv.x, w2r[op * 8 + p4 * 2]);
                        FMA2(acc2[op * 4 + b4], hv.y, w2r[op * 8 + p4 * 2 + 1]);
                    }
                }
            }
            // fold k-pairs, butterfly-reduce 16 values over 32 lanes
            float r[16];
            #pragma unroll
            for (int i = 0; i < 16; i++) r[i] = fold2(acc2[i]);
            {
                int up = lane & 16;
                #pragma unroll
                for (int i = 0; i < 8; i++) {
                    float snd = up ? r[i] : r[i + 8];
                    float kp  = up ? r[i + 8] : r[i];
                    r[i] = kp + __shfl_xor_sync(0xffffffffu, snd, 16);
                }
                up = lane & 8;
                #pragma unroll
                for (int i = 0; i < 4; i++) {
                    float snd = up ? r[i] : r[i + 4];
                    float kp  = up ? r[i + 4] : r[i];
                    r[i] = kp + __shfl_xor_sync(0xffffffffu, snd, 8);
                }
                up = lane & 4;
                #pragma unroll
                for (int i = 0; i < 2; i++) {
                    float snd = up ? r[i] : r[i + 2];
                    float kp  = up ? r[i + 2] : r[i];
                    r[i] = kp + __shfl_xor_sync(0xffffffffu, snd, 4);
                }
                {
                    int u2 = lane & 2;
                    float snd = u2 ? r[0] : r[1];
                    float kp  = u2 ? r[1] : r[0];
                    r[0] = kp + __shfl_xor_sync(0xffffffffu, snd, 2);
                }
                r[0] += __shfl_xor_sync(0xffffffffu, r[0], 1);
            }
            if (!(lane & 1)) {
                int idx = (lane >> 1) & 15;
                int op = idx >> 2, b4 = idx & 3;
                int b = hb * 4 + b4, jl = jlb + op;
                float add = is_rec ? pa_s[par][b][jl] : pc_s[par][b][jl];
                val_s[b][(is_rec ? 0 : 32) + jl] = tanh_f(r[0] + add);
            }
        }
        __syncthreads();

        // stash prefetched tile into the other buffer
        if (pt < S_) {
            if (tid < 256) pa_s[pt & 1][pbb][pjj] = pf;
            else           pc_s[pt & 1][pbb][pjj] = pf;
        }

        // publish f slice (coalesced)
        if (tid < 256) {
            int b = tid >> 5, jj = tid & 31;
            g_f[par][bg * 8 + b][hg * 32 + jj] = val_s[b][jj];
        }
        // per-row partial sums over this j-slice (warp b)
        if (warp < 8) {
            int b = warp;
            float f  = val_s[b][lane];
            float th = val_s[b][lane + 32];
            float h  = h_s[(b << 9) + sw_j];
            float p0 = f, p1 = f * f, p2 = h * f;
            float p3 = th * w2_s[lane], p4 = h, p5 = h * h;
            #pragma unroll
            for (int off = 16; off; off >>= 1) {
                p0 += __shfl_down_sync(0xffffffffu, p0, off);
                p1 += __shfl_down_sync(0xffffffffu, p1, off);
                p2 += __shfl_down_sync(0xffffffffu, p2, off);
                p3 += __shfl_down_sync(0xffffffffu, p3, off);
                p4 += __shfl_down_sync(0xffffffffu, p4, off);
                p5 += __shfl_down_sync(0xffffffffu, p5, off);
            }
            if (lane == 0) {
                g_part4[par][bg * 8 + b][hg][0] = make_float4(p0, p1, p2, p3);
                g_part4[par][bg * 8 + b][hg][1] = make_float4(p4, p5, 0.f, 0.f);
            }
        }

        grid_barrier();     // the ONLY grid sync this step

        // ---- hoisted loads: partials first, then all f rows (overlap L2) ----
        float4 u  = make_float4(0.f, 0.f, 0.f, 0.f);
        float4 v4 = make_float4(0.f, 0.f, 0.f, 0.f);
        if (warp < 8 && lane < 16) {
            u  = __ldcg(&g_part4[par][bg * 8 + warp][lane][0]);
            v4 = __ldcg(&g_part4[par][bg * 8 + warp][lane][1]);
        }
        float f_r[8];
        #pragma unroll
        for (int b = 0; b < 8; b++)
            f_r[b] = __ldcg(&g_f[par][bg * 8 + b][tid]);

        // ---- row stats (data in lanes 0-15 -> tree starts at off=8) ----
        if (warp < 8) {
            float s0 = u.x, s1 = u.y, s2 = u.z, s3r = u.w, s4 = v4.x, s5 = v4.y;
            #pragma unroll
            for (int off = 8; off; off >>= 1) {
                s0  += __shfl_down_sync(0xffffffffu, s0, off);
                s1  += __shfl_down_sync(0xffffffffu, s1, off);
                s2  += __shfl_down_sync(0xffffffffu, s2, off);
                s3r += __shfl_down_sync(0xffffffffu, s3r, off);
                s4  += __shfl_down_sync(0xffffffffu, s4, off);
                s5  += __shfl_down_sync(0xffffffffu, s5, off);
            }
            if (lane == 0) {
                int bG = bg * 8 + warp;
                float tau  = 1.f + 9.f / (1.f + __expf(-(s3r + tb2)));
                float cc   = 0.1f / tau;
                float aa   = 1.f - cc;
                float mean = (aa * s4 + cc * s0) * (1.f / 512.f);
                float ep2  = (aa * aa * s5 + 2.f * aa * cc * s2 + cc * cc * s1)
                             * (1.f / 512.f);
                float rstd = rsqrtf(ep2 - mean * mean + 1e-5f);
                stats_s[warp] = make_float4(aa, cc, mean, rstd);
                if (hg == 0) tauh[(size_t)bG * S_ + t] = tau;
            }
        }
        __syncthreads();

        // ---- reconstruct full h_new rows; write own output slice ----
        #pragma unroll
        for (int b = 0; b < 8; b++) {
            float4 st = stats_s[b];
            float h = h_s[(b << 9) + sw_tid];
            float p  = st.x * h + st.y * f_r[b];
            float hn = (p - st.z) * st.w * gam + bet;
            h_s[(b << 9) + sw_tid] = hn;
            if ((tid >> 5) == hg) {
                out[((size_t)(bg * 8 + b) * S_ + t) * H_ + tid] = hn;
                if (t == S_ - 1) hfin[(size_t)(bg * 8 + b) * H_ + tid] = hn;
            }
        }
        __syncthreads();   // h_s reuse ordering for next step
    }
}

// =============================================================================
extern "C" void kernel_launch(void* const* d_in, const int* in_sizes, int n_in,
                              void* d_out, int out_size)
{
    const float* x     = (const float*)d_in[0];
    const float* h0    = (const float*)d_in[1];
    const float* W_in  = (const float*)d_in[2];
    const float* b_in  = (const float*)d_in[3];
    const float* W_rec = (const float*)d_in[4];
    const float* tw1   = (const float*)d_in[5];
    const float* tb1   = (const float*)d_in[6];
    const float* tw2   = (const float*)d_in[7];
    const float* tb2   = (const float*)d_in[8];
    const float* gamma = (const float*)d_in[9];
    const float* beta  = (const float*)d_in[10];

    float* out  = (float*)d_out;                       // [B, S, H]
    float* hfin = out + (size_t)B_ * S_ * H_;          // [B, H]
    float* tauh = hfin + (size_t)B_ * H_;              // [B, S, 1]

    cudaFuncSetAttribute(precompute_gemm_tf32,
                         cudaFuncAttributeMaxDynamicSharedMemorySize, GSM);
    precompute_gemm_tf32<<<dim3(512, 8), 256, GSM>>>(x, W_in, b_in, tw1, tb1);
    liquid_recurrent<<<NC, 512>>>(h0, W_rec, tw1, tw2, tb2, gamma, beta,
                                  out, hfin, tauh);
}

// round 15
// speedup vs baseline: 1.1044x; 1.0011x over previous
#include <cuda_runtime.h>
#include <cstdint>

#define S_  1024
#define B_  64
#define I_  256
#define H_  512
#define NC  128      // persistent CTAs (16 h-groups x 8 b-groups)
#define NHG 16

// ---------------- scratch (static __device__ — no allocation) ----------------
__device__ float  g_A[(size_t)S_ * B_ * H_];      // x @ W_in.T + b_in      [t*64+b][j]
__device__ float  g_C[(size_t)S_ * B_ * H_];      // x @ tau_w1[:,:I].T+b1  [t*64+b][j]
__device__ float  g_f[2][B_][H_];                 // tanh(u) exchange, double-buffered
__device__ float4 g_part4[2][B_][NHG][2];         // 6 partial sums per (b, hgroup)
__device__ unsigned long long g_tickets;          // barrier arrivals (monotonic u64)

// ---- packed fp32x2 helpers (Blackwell dual-issue fp32) ----
#define FMA2(d, a, b) \
    asm("fma.rn.f32x2 %0, %1, %2, %0;" : "+l"(d) : "l"(a), "l"(b))

__device__ __forceinline__ unsigned long long pk2(float a, float b) {
    return (unsigned long long)__float_as_uint(a) |
           ((unsigned long long)__float_as_uint(b) << 32);
}
__device__ __forceinline__ float fold2(unsigned long long v) {
    return __uint_as_float((unsigned)v) + __uint_as_float((unsigned)(v >> 32));
}
// XOR swizzle on a 512-float h row (16B granularity) -> conflict-free LDS.128
__device__ __forceinline__ int hswz(int f) {
    int u = f >> 2;
    u ^= (u >> 3) & 7;
    return (u << 2) | (f & 3);
}
// fast tanh: (1 - e^{-2|x|}) / (1 + e^{-2|x|}), sign-restored (~1e-6 abs err)
__device__ __forceinline__ float tanh_f(float x) {
    float e = __expf(-2.f * fabsf(x));
    float t = __fdividef(1.f - e, 1.f + e);
    return copysignf(t, x);
}
__device__ __forceinline__ unsigned f2tf32(float f) {
    unsigned u;
    asm("cvt.rna.tf32.f32 %0, %1;" : "=r"(u) : "f"(f));
    return u;
}

// =============================================================================
// Kernel 1: time-parallel precompute GEMM on TENSOR CORES (tf32 mma.sync).
//   out[r, n] = sum_k x_row(r)[k] * W'(n)[k] + bias(n), r in [0,65536), n [0,1024)
//   CTA tile: BM=128 (r), BN=128 (n), K=256 in two 128-chunks. 256 threads.
//   SMEM rows use a PAIRED k layout: within each k8 block, position 2c holds
//   logical k=c and 2c+1 holds k=c+4 -> every mma fragment is one LDS.64.
// =============================================================================
#define GROW 132                          // padded row stride (floats/uints)
#define GSM  (2 * 128 * GROW * 4)         // xs + ws

__global__ __launch_bounds__(256) void precompute_gemm_tf32(
    const float* __restrict__ x, const float* __restrict__ W_in,
    const float* __restrict__ b_in, const float* __restrict__ tau_w1,
    const float* __restrict__ tau_b1)
{
    extern __shared__ __align__(16) unsigned gsm[];
    unsigned* xs = gsm;                   // [128][GROW]
    unsigned* ws = gsm + 128 * GROW;      // [128][GROW]

    const int tid   = threadIdx.x;
    const int mtile = blockIdx.x;         // 0..511  (128 r each)
    const int nbase = blockIdx.y * 128;   // 0..896
    const int warp  = tid >> 5, lane = tid & 31;
    const int gid   = lane >> 2, tig = lane & 3;
    const int wm    = warp & 3;           // m-quadrant (32 rows)
    const int wn    = warp >> 2;          // n-half (64 cols)

    float acc[2][8][4];
    #pragma unroll
    for (int mt = 0; mt < 2; mt++)
        #pragma unroll
        for (int nt = 0; nt < 8; nt++)
            #pragma unroll
            for (int c = 0; c < 4; c++) acc[mt][nt][c] = 0.f;

    const int srow = tid >> 1;            // staging row 0..127
    const int shalf = tid & 1;            // k-half of the chunk

    for (int kc = 0; kc < 2; kc++) {
        // ---- stage x chunk (tf32-converted, paired layout) ----
        {
            int r = mtile * 128 + srow;
            int t = r >> 6, b = r & 63;
            const float* src = x + ((size_t)b * S_ + t) * I_ + kc * 128 + shalf * 64;
            unsigned* dst = xs + srow * GROW;
            #pragma unroll
            for (int i = 0; i < 16; i++) {
                int k0 = shalf * 64 + i * 4;
                float4 v = *(const float4*)(src + i * 4);
                int blk = k0 >> 3, odd = (k0 >> 2) & 1;
                int p = blk * 8 + odd;
                dst[p]     = f2tf32(v.x);
                dst[p + 2] = f2tf32(v.y);
                dst[p + 4] = f2tf32(v.z);
                dst[p + 6] = f2tf32(v.w);
            }
        }
        // ---- stage weights chunk ----
        {
            int ng = nbase + srow;
            const float* src = (ng < 512)
                ? (W_in + (size_t)ng * I_)
                : (tau_w1 + (size_t)(ng - 512) * (I_ + H_));
            src += kc * 128 + shalf * 64;
            unsigned* dst = ws + srow * GROW;
            #pragma unroll
            for (int i = 0; i < 16; i++) {
                int k0 = shalf * 64 + i * 4;
                float4 v = *(const float4*)(src + i * 4);
                int blk = k0 >> 3, odd = (k0 >> 2) & 1;
                int p = blk * 8 + odd;
                dst[p]     = f2tf32(v.x);
                dst[p + 2] = f2tf32(v.y);
                dst[p + 4] = f2tf32(v.z);
                dst[p + 6] = f2tf32(v.w);
            }
        }
        __syncthreads();

        // ---- mma main loop: 16 k8 steps per chunk ----
        #pragma unroll 4
        for (int ks = 0; ks < 16; ks++) {
            int poff = ks * 8 + 2 * tig;
            unsigned a0[2], a1[2], a2[2], a3[2];
            #pragma unroll
            for (int mt = 0; mt < 2; mt++) {
                int row = wm * 32 + mt * 16 + gid;
                uint2 lo = *(const uint2*)(xs + row * GROW + poff);
                uint2 hi = *(const uint2*)(xs + (row + 8) * GROW + poff);
                a0[mt] = lo.x; a2[mt] = lo.y;   // (g, tig), (g, tig+4)
                a1[mt] = hi.x; a3[mt] = hi.y;   // (g+8, tig), (g+8, tig+4)
            }
            #pragma unroll
            for (int nt = 0; nt < 8; nt++) {
                int nrow = wn * 64 + nt * 8 + gid;
                uint2 bq = *(const uint2*)(ws + nrow * GROW + poff);
                #pragma unroll
                for (int mt = 0; mt < 2; mt++) {
                    asm volatile(
                        "mma.sync.aligned.m16n8k8.row.col.f32.tf32.tf32.f32 "
                        "{%0,%1,%2,%3}, {%4,%5,%6,%7}, {%8,%9}, {%0,%1,%2,%3};"
                        : "+f"(acc[mt][nt][0]), "+f"(acc[mt][nt][1]),
                          "+f"(acc[mt][nt][2]), "+f"(acc[mt][nt][3])
                        : "r"(a0[mt]), "r"(a1[mt]), "r"(a2[mt]), "r"(a3[mt]),
                          "r"(bq.x), "r"(bq.y));
                }
            }
        }
        __syncthreads();
    }

    // ---- epilogue: add bias, route to g_A / g_C ----
    #pragma unroll
    for (int nt = 0; nt < 8; nt++) {
        int ng = nbase + wn * 64 + nt * 8 + 2 * tig;           // even
        float2 bias = (ng < 512) ? *(const float2*)(b_in + ng)
                                 : *(const float2*)(tau_b1 + (ng - 512));
        #pragma unroll
        for (int mt = 0; mt < 2; mt++) {
            int r0 = mtile * 128 + wm * 32 + mt * 16 + gid;
            float2 v0 = make_float2(acc[mt][nt][0] + bias.x,
                                    acc[mt][nt][1] + bias.y);
            float2 v1 = make_float2(acc[mt][nt][2] + bias.x,
                                    acc[mt][nt][3] + bias.y);
            if (ng < 512) {
                *(float2*)(g_A + (size_t)r0 * H_ + ng)       = v0;
                *(float2*)(g_A + (size_t)(r0 + 8) * H_ + ng) = v1;
            } else {
                *(float2*)(g_C + (size_t)r0 * H_ + (ng - 512))       = v0;
                *(float2*)(g_C + (size_t)(r0 + 8) * H_ + (ng - 512)) = v1;
            }
        }
    }
}

// =============================================================================
// Kernel 2: persistent recurrent scan — EXACT champion (R9, 5286us):
//   128 CTAs x 512, single ticket barrier, register weights, fast tanh,
//   hoisted post-barrier loads. Only delta: stats tree starts at off=8
//   (partials live in lanes 0-15; off=16 round added zeros).
// =============================================================================
__device__ __forceinline__ void grid_barrier()
{
    __syncthreads();
    if (threadIdx.x == 0) {
        unsigned long long prev;
        asm volatile("atom.release.gpu.add.u64 %0, [%1], %2;"
                     : "=l"(prev) : "l"(&g_tickets), "l"(1ULL) : "memory");
        unsigned long long target = (prev & ~127ULL) + 128ULL;
        unsigned long long cur;
        do {
            asm volatile("ld.acquire.gpu.u64 %0, [%1];"
                         : "=l"(cur) : "l"(&g_tickets) : "memory");
        } while (cur < target);
    }
    __syncthreads();
}

__global__ __launch_bounds__(512, 1) void liquid_recurrent(
    const float* __restrict__ h0,     const float* __restrict__ W_rec,
    const float* __restrict__ tau_w1, const float* __restrict__ tau_w2,
    const float* __restrict__ tau_b2, const float* __restrict__ gamma,
    const float* __restrict__ beta,
    float* __restrict__ out, float* __restrict__ hfin, float* __restrict__ tauh)
{
    __shared__ __align__(16) float h_s[8 * H_];     // swizzled h rows (16 KB)
    __shared__ float  pa_s[2][8][32];               // A tiles, double-buffered
    __shared__ float  pc_s[2][8][32];               // C tiles, double-buffered
    __shared__ float  val_s[8][64];                 // f (o<32) / t_hid (o>=32)
    __shared__ float4 stats_s[8];                   // {a, c, mean, rstd}
    __shared__ float  gam_s[H_], bet_s[H_];
    __shared__ float  w2_s[32];

    const int tid  = threadIdx.x;
    const int hg   = blockIdx.x & 15;
    const int bg   = blockIdx.x >> 4;
    const int warp = tid >> 5, lane = tid & 31;
    const bool is_rec = (warp < 8);
    const int jlb  = (warp & 7) * 4;                // jl base for this warp

    // ---- recurrent weights -> registers as f32x2 k-pairs (64 regs) ----
    unsigned long long w2r[32];
    {
        #pragma unroll
        for (int op = 0; op < 4; op++) {
            int j = hg * 32 + jlb + op;
            const float* wr = is_rec ? (W_rec + (size_t)j * H_)
                                     : (tau_w1 + (size_t)j * (I_ + H_) + I_);
            #pragma unroll
            for (int p4 = 0; p4 < 4; p4++) {
                float4 v = *(const float4*)(wr + lane * 16 + p4 * 4);
                w2r[op * 8 + p4 * 2]     = pk2(v.x, v.y);
                w2r[op * 8 + p4 * 2 + 1] = pk2(v.z, v.w);
            }
        }
    }
    const int s3 = (lane >> 1) & 7;
    int hoff[4];
    #pragma unroll
    for (int p4 = 0; p4 < 4; p4++) hoff[p4] = ((lane * 4 + p4) ^ s3) << 2;
    const int sw_tid = hswz(tid);
    const int sw_j   = hswz(hg * 32 + lane);

    gam_s[tid] = gamma[tid];
    bet_s[tid] = beta[tid];
    if (tid < 32) w2_s[tid] = tau_w2[hg * 32 + tid];
    const float tb2 = tau_b2[0];
    #pragma unroll
    for (int b = 0; b < 8; b++)
        h_s[(b << 9) + sw_tid] = h0[(size_t)(bg * 8 + b) * H_ + tid];
    // prologue: tiles for t=0
    {
        int bb = (tid & 255) >> 5, jj = tid & 31;
        size_t base = ((size_t)(bg * 8 + bb)) * H_ + hg * 32 + jj;
        if (tid < 256) pa_s[0][bb][jj] = g_A[base];
        else           pc_s[0][bb][jj] = g_C[base];
    }
    __syncthreads();

    const float gam = gam_s[tid], bet = bet_s[tid];

    for (int t = 0; t < S_; t++) {
        const int par = t & 1;

        // prefetch next step's A/C tile into registers (DRAM latency hidden)
        float pf = 0.f;
        const int pt = t + 1;
        const int pbb = (tid & 255) >> 5, pjj = tid & 31;
        if (pt < S_) {
            size_t base = ((size_t)pt * B_ + bg * 8 + pbb) * H_ + hg * 32 + pjj;
            pf = (tid < 256) ? g_A[base] : g_C[base];
        }

        // ---- GEMV: 4 outputs/warp, 16 k per lane, fp32x2 ----
        #pragma unroll
        for (int hb = 0; hb < 2; hb++) {
            unsigned long long acc2[16];
            #pragma unroll
            for (int i = 0; i < 16; i++) acc2[i] = 0ULL;
            #pragma unroll
            for (int b4 = 0; b4 < 4; b4++) {
                const float* hp = h_s + ((hb * 4 + b4) << 9);
                #pragma unroll
                for (int p4 = 0; p4 < 4; p4++) {
                    ulonglong2 hv = *(const ulonglong2*)(hp + hoff[p4]);
                    #pragma unroll
                    for (int op = 0; op < 4; op++) {
                        FMA2(acc2[op * 4 + b4], hv.x, w2r[op * 8 + p4 * 2]);
                        FMA2(acc2[op * 4 + b4], hv.y, w2r[op * 8 + p4 * 2 + 1]);
                    }
                }
            }
            // fold k-pairs, butterfly-reduce 16 values over 32 lanes
            float r[16];
            #pragma unroll
            for (int i = 0; i < 16; i++) r[i] = fold2(acc2[i]);
            {
                int up = lane & 16;
                #pragma unroll
                for (int i = 0; i < 8; i++) {
                    float snd = up ? r[i] : r[i + 8];
                    float kp  = up ? r[i + 8] : r[i];
                    r[i] = kp + __shfl_xor_sync(0xffffffffu, snd, 16);
                }
                up = lane & 8;
                #pragma unroll
                for (int i = 0; i < 4; i++) {
                    float snd = up ? r[i] : r[i + 4];
                    float kp  = up ? r[i + 4] : r[i];
                    r[i] = kp + __shfl_xor_sync(0xffffffffu, snd, 8);
                }
                up = lane & 4;
                #pragma unroll
                for (int i = 0; i < 2; i++) {
                    float snd = up ? r[i] : r[i + 2];
                    float kp  = up ? r[i + 2] : r[i];
                    r[i] = kp + __shfl_xor_sync(0xffffffffu, snd, 4);
                }
                {
                    int u2 = lane & 2;
                    float snd = u2 ? r[0] : r[1];
                    float kp  = u2 ? r[1] : r[0];
                    r[0] = kp + __shfl_xor_sync(0xffffffffu, snd, 2);
                }
                r[0] += __shfl_xor_sync(0xffffffffu, r[0], 1);
            }
            if (!(lane & 1)) {
                int idx = (lane >> 1) & 15;
                int op = idx >> 2, b4 = idx & 3;
                int b = hb * 4 + b4, jl = jlb + op;
                float add = is_rec ? pa_s[par][b][jl] : pc_s[par][b][jl];
                val_s[b][(is_rec ? 0 : 32) + jl] = tanh_f(r[0] + add);
            }
        }
        __syncthreads();

        // stash prefetched tile into the other buffer
        if (pt < S_) {
            if (tid < 256) pa_s[pt & 1][pbb][pjj] = pf;
            else           pc_s[pt & 1][pbb][pjj] = pf;
        }

        // publish f slice (coalesced)
        if (tid < 256) {
            int b = tid >> 5, jj = tid & 31;
            g_f[par][bg * 8 + b][hg * 32 + jj] = val_s[b][jj];
        }
        // per-row partial sums over this j-slice (warp b)
        if (warp < 8) {
            int b = warp;
            float f  = val_s[b][lane];
            float th = val_s[b][lane + 32];
            float h  = h_s[(b << 9) + sw_j];
            float p0 = f, p1 = f * f, p2 = h * f;
            float p3 = th * w2_s[lane], p4 = h, p5 = h * h;
            #pragma unroll
            for (int off = 16; off; off >>= 1) {
                p0 += __shfl_down_sync(0xffffffffu, p0, off);
                p1 += __shfl_down_sync(0xffffffffu, p1, off);
                p2 += __shfl_down_sync(0xffffffffu, p2, off);
                p3 += __shfl_down_sync(0xffffffffu, p3, off);
                p4 += __shfl_down_sync(0xffffffffu, p4, off);
                p5 += __shfl_down_sync(0xffffffffu, p5, off);
            }
            if (lane == 0) {
                g_part4[par][bg * 8 + b][hg][0] = make_float4(p0, p1, p2, p3);
                g_part4[par][bg * 8 + b][hg][1] = make_float4(p4, p5, 0.f, 0.f);
            }
        }

        grid_barrier();     // the ONLY grid sync this step

        // ---- hoisted loads: partials first, then all f rows (overlap L2) ----
        float4 u  = make_float4(0.f, 0.f, 0.f, 0.f);
        float4 v4 = make_float4(0.f, 0.f, 0.f, 0.f);
        if (warp < 8 && lane < 16) {
            u  = __ldcg(&g_part4[par][bg * 8 + warp][lane][0]);
            v4 = __ldcg(&g_part4[par][bg * 8 + warp][lane][1]);
        }
        float f_r[8];
        #pragma unroll
        for (int b = 0; b < 8; b++)
            f_r[b] = __ldcg(&g_f[par][bg * 8 + b][tid]);

        // ---- row stats (data in lanes 0-15 -> tree starts at off=8) ----
        if (warp < 8) {
            float s0 = u.x, s1 = u.y, s2 = u.z, s3r = u.w, s4 = v4.x, s5 = v4.y;
            #pragma unroll
            for (int off = 8; off; off >>= 1) {
                s0  += __shfl_down_sync(0xffffffffu, s0, off);
                s1  += __shfl_down_sync(0xffffffffu, s1, off);
                s2  += __shfl_down_sync(0xffffffffu, s2, off);
                s3r += __shfl_down_sync(0xffffffffu, s3r, off);
                s4  += __shfl_down_sync(0xffffffffu, s4, off);
                s5  += __shfl_down_sync(0xffffffffu, s5, off);
            }
            if (lane == 0) {
                int bG = bg * 8 + warp;
                float tau  = 1.f + 9.f / (1.f + __expf(-(s3r + tb2)));
                float cc   = 0.1f / tau;
                float aa   = 1.f - cc;
                float mean = (aa * s4 + cc * s0) * (1.f / 512.f);
                float ep2  = (aa * aa * s5 + 2.f * aa * cc * s2 + cc * cc * s1)
                             * (1.f / 512.f);
                float rstd = rsqrtf(ep2 - mean * mean + 1e-5f);
                stats_s[warp] = make_float4(aa, cc, mean, rstd);
                if (hg == 0) tauh[(size_t)bG * S_ + t] = tau;
            }
        }
        __syncthreads();

        // ---- reconstruct full h_new rows; write own output slice ----
        #pragma unroll
        for (int b = 0; b < 8; b++) {
            float4 st = stats_s[b];
            float h = h_s[(b << 9) + sw_tid];
            float p  = st.x * h + st.y * f_r[b];
            float hn = (p - st.z) * st.w * gam + bet;
            h_s[(b << 9) + sw_tid] = hn;
            if ((tid >> 5) == hg) {
                out[((size_t)(bg * 8 + b) * S_ + t) * H_ + tid] = hn;
                if (t == S_ - 1) hfin[(size_t)(bg * 8 + b) * H_ + tid] = hn;
            }
        }
        __syncthreads();   // h_s reuse ordering for next step
    }
}

// =============================================================================
extern "C" void kernel_launch(void* const* d_in, const int* in_sizes, int n_in,
                              void* d_out, int out_size)
{
    const float* x     = (const float*)d_in[0];
    const float* h0    = (const float*)d_in[1];
    const float* W_in  = (const float*)d_in[2];
    const float* b_in  = (const float*)d_in[3];
    const float* W_rec = (const float*)d_in[4];
    const float* tw1   = (const float*)d_in[5];
    const float* tb1   = (const float*)d_in[6];
    const float* tw2   = (const float*)d_in[7];
    const float* tb2   = (const float*)d_in[8];
    const float* gamma = (const float*)d_in[9];
    const float* beta  = (const float*)d_in[10];

    float* out  = (float*)d_out;                       // [B, S, H]
    float* hfin = out + (size_t)B_ * S_ * H_;          // [B, H]
    float* tauh = hfin + (size_t)B_ * H_;              // [B, S, 1]

    cudaFuncSetAttribute(precompute_gemm_tf32,
                         cudaFuncAttributeMaxDynamicSharedMemorySize, GSM);
    precompute_gemm_tf32<<<dim3(512, 8), 256, GSM>>>(x, W_in, b_in, tw1, tb1);
    liquid_recurrent<<<NC, 512>>>(h0, W_rec, tw1, tw2, tb2, gamma, beta,
                                  out, hfin, tauh);
}